// round 2
// baseline (speedup 1.0000x reference)
#include <cuda_runtime.h>
#include <cstdint>

#define N_NODES 50000
#define N_EDGES 1600000
#define F_INDIM 128
#define HID     64
#define NCLS    19
#define NGRAPH  512

// ---- scratch (static device globals; no allocation) ----
__device__ float g_deg [N_NODES];
__device__ float g_dinv[N_NODES];
__device__ float g_a   [N_NODES * HID];   // gemm output / gather source
__device__ float g_b   [N_NODES * HID];   // aggregation target / activations
__device__ float g_pool[NGRAPH * HID];
__device__ float g_cnt [NGRAPH];

// ---------------------------------------------------------------------------
__global__ void k_deg_init() {
    int i = blockIdx.x * blockDim.x + threadIdx.x;
    if (i < N_NODES) g_deg[i] = 1.0f;   // self-loop contributes 1
}

__global__ void k_deg_edges(const int* __restrict__ ei) {
    int e = blockIdx.x * blockDim.x + threadIdx.x;
    if (e < N_EDGES) {
        int d = ei[N_EDGES + e];  // dst row
        atomicAdd(&g_deg[d], 1.0f);
    }
}

__global__ void k_dinv() {
    int i = blockIdx.x * blockDim.x + threadIdx.x;
    if (i < N_NODES) g_dinv[i] = rsqrtf(g_deg[i]);
}

// ---------------------------------------------------------------------------
// GEMM: out[N, 64] = X[N, K] @ W[K, 64]. Block = 256 threads = 16 nodes,
// each thread produces 4 contiguous output columns. W cached in smem.
template <int K>
__global__ void k_gemm(const float* __restrict__ X, const float* __restrict__ W,
                       float* __restrict__ out) {
    __shared__ float Ws[K * HID];
    __shared__ float Xs[16 * K];
    const int tid = threadIdx.x;
    const int nb  = blockIdx.x * 16;

    for (int i = tid; i < K * HID; i += 256) Ws[i] = W[i];
    for (int i = tid; i < 16 * K; i += 256) {
        int n = nb + i / K;
        Xs[i] = (n < N_NODES) ? X[n * K + (i % K)] : 0.0f;
    }
    __syncthreads();

    const int ln   = tid / 16;            // 0..15 local node
    const int node = nb + ln;
    const int c0   = (tid & 15) * 4;      // 4 output cols
    if (node >= N_NODES) return;

    float4 acc = make_float4(0.f, 0.f, 0.f, 0.f);
    #pragma unroll 8
    for (int k = 0; k < K; ++k) {
        float xv = Xs[ln * K + k];
        float4 w = *reinterpret_cast<const float4*>(&Ws[k * HID + c0]);
        acc.x += xv * w.x; acc.y += xv * w.y;
        acc.z += xv * w.z; acc.w += xv * w.w;
    }
    *reinterpret_cast<float4*>(&out[node * HID + c0]) = acc;
}

// ---------------------------------------------------------------------------
// Self-loop term initializes the aggregation buffer: agg[i] = h[i] * dinv[i]^2
__global__ void k_selfloop() {
    int idx = blockIdx.x * blockDim.x + threadIdx.x;
    if (idx < N_NODES * HID) {
        int n = idx / HID;
        float di = g_dinv[n];
        g_b[idx] = g_a[idx] * di * di;
    }
}

// Warp per edge: gather 64 floats from g_a[src], scale, atomic-scatter to g_b[dst].
__global__ void k_agg(const int* __restrict__ ei) {
    int gt   = blockIdx.x * blockDim.x + threadIdx.x;
    int e    = gt >> 5;
    int lane = gt & 31;
    if (e >= N_EDGES) return;
    int s = ei[e];
    int d = ei[N_EDGES + e];
    float norm = g_dinv[s] * g_dinv[d];
    const float* hs = &g_a[s * HID];
    float*       hd = &g_b[d * HID];
    atomicAdd(&hd[lane],      hs[lane]      * norm);
    atomicAdd(&hd[lane + 32], hs[lane + 32] * norm);
}

__global__ void k_bias_relu(const float* __restrict__ bias) {
    int idx = blockIdx.x * blockDim.x + threadIdx.x;
    if (idx < N_NODES * HID) {
        float v = g_b[idx] + bias[idx % HID];
        g_b[idx] = v > 0.f ? v : 0.f;
    }
}

// ---------------------------------------------------------------------------
__global__ void k_pool_zero() {
    int i = blockIdx.x * blockDim.x + threadIdx.x;
    if (i < NGRAPH * HID) g_pool[i] = 0.f;
    if (i < NGRAPH)       g_cnt[i]  = 0.f;
}

// Warp per node: accumulate its 64 features into its graph's pool row.
__global__ void k_pool(const int* __restrict__ batch) {
    int gt   = blockIdx.x * blockDim.x + threadIdx.x;
    int n    = gt >> 5;
    int lane = gt & 31;
    if (n >= N_NODES) return;
    int g = batch[n];
    atomicAdd(&g_pool[g * HID + lane],      g_b[n * HID + lane]);
    atomicAdd(&g_pool[g * HID + lane + 32], g_b[n * HID + lane + 32]);
    if (lane == 0) atomicAdd(&g_cnt[g], 1.0f);
}

// Warp per graph: out[g, c] = (mean(agg) + b2) @ W_out + b_out
__global__ void k_final(const float* __restrict__ b2,
                        const float* __restrict__ Wout,
                        const float* __restrict__ bout,
                        float* __restrict__ out) {
    int gt   = blockIdx.x * blockDim.x + threadIdx.x;
    int g    = gt >> 5;
    int lane = gt & 31;
    if (g >= NGRAPH || lane >= NCLS) return;
    float cnt = g_cnt[g];
    float inv = cnt > 0.f ? 1.0f / cnt : 0.0f;   // matches max(cnt,1) since sums=0 when cnt=0
    float has = cnt > 0.f ? 1.0f : 0.0f;
    float acc = bout[lane];
    #pragma unroll
    for (int h = 0; h < HID; ++h) {
        float ph = g_pool[g * HID + h] * inv + has * b2[h];
        acc += ph * Wout[h * NCLS + lane];
    }
    out[g * NCLS + lane] = acc;
}

// ---------------------------------------------------------------------------
extern "C" void kernel_launch(void* const* d_in, const int* in_sizes, int n_in,
                              void* d_out, int out_size) {
    const float* x    = (const float*)d_in[0];
    const int*   ei   = (const int*)  d_in[1];   // int32: JAX x64 disabled
    const int*   bat  = (const int*)  d_in[2];
    const float* W1   = (const float*)d_in[3];
    const float* b1   = (const float*)d_in[4];
    const float* W2   = (const float*)d_in[5];
    const float* b2   = (const float*)d_in[6];
    const float* Wout = (const float*)d_in[7];
    const float* bout = (const float*)d_in[8];
    float* out = (float*)d_out;

    float* pa;  cudaGetSymbolAddress((void**)&pa, g_a);
    float* pb;  cudaGetSymbolAddress((void**)&pb, g_b);

    const int TB = 256;
    const int nblkN   = (N_NODES + TB - 1) / TB;
    const int nblkE   = (N_EDGES + TB - 1) / TB;
    const int nblkNH  = (N_NODES * HID + TB - 1) / TB;
    const int nblkAgg = (N_EDGES * 32 + TB - 1) / TB;
    const int nblkPo  = (N_NODES * 32 + TB - 1) / TB;

    // degrees / norm
    k_deg_init <<<nblkN, TB>>>();
    k_deg_edges<<<nblkE, TB>>>(ei);
    k_dinv     <<<nblkN, TB>>>();

    // layer 1: h = relu( GCNConv(x, W1) + b1 )
    k_gemm<F_INDIM><<<(N_NODES + 15) / 16, TB>>>(x, W1, pa);
    k_selfloop <<<nblkNH, TB>>>();
    k_agg      <<<nblkAgg, TB>>>(ei);
    k_bias_relu<<<nblkNH, TB>>>(b1);

    // layer 2: h = GCNConv(h, W2)  (b2 folded into pooling head)
    k_gemm<HID><<<(N_NODES + 15) / 16, TB>>>(pb, W2, pa);
    k_selfloop <<<nblkNH, TB>>>();
    k_agg      <<<nblkAgg, TB>>>(ei);

    // global mean pool + linear head
    k_pool_zero<<<(NGRAPH * HID + TB - 1) / TB, TB>>>();
    k_pool     <<<nblkPo, TB>>>(bat);
    k_final    <<<(NGRAPH * 32 + TB - 1) / TB, TB>>>(b2, Wout, bout, out);
}

// round 3
// speedup vs baseline: 1.1433x; 1.1433x over previous
#include <cuda_runtime.h>
#include <cstdint>

#define N_NODES 50000
#define N_EDGES 1600000
#define F_INDIM 128
#define HID     64
#define NCLS    19
#define NGRAPH  512

// ---- scratch (static device globals; no allocation) ----
__device__ float g_deg [N_NODES];
__device__ float g_dinv[N_NODES];
__device__ float g_a   [N_NODES * HID];   // gemm output / gather source
__device__ float g_b   [N_NODES * HID];   // aggregation target / activations
__device__ float g_pool[NGRAPH * HID];
__device__ float g_cnt [NGRAPH];

// ---------------------------------------------------------------------------
__global__ void k_deg_init() {
    int i = blockIdx.x * blockDim.x + threadIdx.x;
    if (i < N_NODES) g_deg[i] = 1.0f;   // self-loop contributes 1
}

__global__ void k_deg_edges(const int* __restrict__ ei) {
    int e = blockIdx.x * blockDim.x + threadIdx.x;
    if (e < N_EDGES) atomicAdd(&g_deg[ei[N_EDGES + e]], 1.0f);
}

__global__ void k_dinv() {
    int i = blockIdx.x * blockDim.x + threadIdx.x;
    if (i < N_NODES) g_dinv[i] = rsqrtf(g_deg[i]);
}

// ---------------------------------------------------------------------------
// Register-tiled GEMM + fused epilogue.
//   out_a[n, 64] = act(X[n, K]) @ W[K, 64]
//   out_b[n, 64] = out_a[n, :] * dinv[n]^2          (self-loop init)
// act = relu(x + bias) when BIAS_RELU (layer 2 input), identity otherwise.
// Block = 256 threads = 64 nodes x 64 cols; thread tile = 4 nodes x 4 cols.
template <int K, bool BIAS_RELU>
__global__ void k_gemm_fused(const float* X, const float* __restrict__ W,
                             const float* __restrict__ bias,
                             float* out_a, float* out_b) {
    constexpr int XP = K + 4;             // padded pitch: spreads node rows over banks
    __shared__ float Xs[64 * XP];
    __shared__ float Ws[K * HID];
    const int tid = threadIdx.x;
    const int nb  = blockIdx.x * 64;

    for (int i = tid; i < K * HID; i += 256) Ws[i] = W[i];
    for (int i = tid; i < 64 * K; i += 256) {
        int nl = i / K, k = i % K;
        int node = nb + nl;
        float v = (node < N_NODES) ? X[node * K + k] : 0.0f;
        if (BIAS_RELU) { v += bias[k]; v = v > 0.f ? v : 0.f; }
        Xs[nl * XP + k] = v;
    }
    __syncthreads();

    const int ny0 = (tid / 16) * 4;       // 4 local nodes
    const int c0  = (tid & 15) * 4;       // 4 output cols

    float4 acc[4];
    #pragma unroll
    for (int i = 0; i < 4; ++i) acc[i] = make_float4(0.f, 0.f, 0.f, 0.f);

    #pragma unroll 4
    for (int k = 0; k < K; k += 4) {
        float4 xr[4], wr[4];
        #pragma unroll
        for (int i = 0; i < 4; ++i)
            xr[i] = *reinterpret_cast<const float4*>(&Xs[(ny0 + i) * XP + k]);
        #pragma unroll
        for (int j = 0; j < 4; ++j)
            wr[j] = *reinterpret_cast<const float4*>(&Ws[(k + j) * HID + c0]);
        #pragma unroll
        for (int i = 0; i < 4; ++i) {
            const float xk0 = xr[i].x, xk1 = xr[i].y, xk2 = xr[i].z, xk3 = xr[i].w;
            acc[i].x += xk0*wr[0].x + xk1*wr[1].x + xk2*wr[2].x + xk3*wr[3].x;
            acc[i].y += xk0*wr[0].y + xk1*wr[1].y + xk2*wr[2].y + xk3*wr[3].y;
            acc[i].z += xk0*wr[0].z + xk1*wr[1].z + xk2*wr[2].z + xk3*wr[3].z;
            acc[i].w += xk0*wr[0].w + xk1*wr[1].w + xk2*wr[2].w + xk3*wr[3].w;
        }
    }

    #pragma unroll
    for (int i = 0; i < 4; ++i) {
        int node = nb + ny0 + i;
        if (node >= N_NODES) break;
        *reinterpret_cast<float4*>(&out_a[node * HID + c0]) = acc[i];
        float di = g_dinv[node]; di *= di;
        float4 b = make_float4(acc[i].x*di, acc[i].y*di, acc[i].z*di, acc[i].w*di);
        *reinterpret_cast<float4*>(&out_b[node * HID + c0]) = b;
    }
}

// ---------------------------------------------------------------------------
// Warp per edge: gather 64 floats from g_a[src], scale, atomic-scatter to g_b[dst].
__global__ void k_agg(const int* __restrict__ ei) {
    int gt   = blockIdx.x * blockDim.x + threadIdx.x;
    int e    = gt >> 5;
    int lane = gt & 31;
    if (e >= N_EDGES) return;
    int s = ei[e];
    int d = ei[N_EDGES + e];
    float norm = g_dinv[s] * g_dinv[d];
    const float* hs = &g_a[s * HID];
    float*       hd = &g_b[d * HID];
    atomicAdd(&hd[lane],      hs[lane]      * norm);
    atomicAdd(&hd[lane + 32], hs[lane + 32] * norm);
}

// ---------------------------------------------------------------------------
__global__ void k_pool_zero() {
    int i = blockIdx.x * blockDim.x + threadIdx.x;
    if (i < NGRAPH * HID) g_pool[i] = 0.f;
    if (i < NGRAPH)       g_cnt[i]  = 0.f;
}

// Warp per node: accumulate its 64 features into its graph's pool row.
__global__ void k_pool(const int* __restrict__ batch) {
    int gt   = blockIdx.x * blockDim.x + threadIdx.x;
    int n    = gt >> 5;
    int lane = gt & 31;
    if (n >= N_NODES) return;
    int g = batch[n];
    atomicAdd(&g_pool[g * HID + lane],      g_b[n * HID + lane]);
    atomicAdd(&g_pool[g * HID + lane + 32], g_b[n * HID + lane + 32]);
    if (lane == 0) atomicAdd(&g_cnt[g], 1.0f);
}

// Warp per graph: out[g, c] = (mean(agg) + b2) @ W_out + b_out
__global__ void k_final(const float* __restrict__ b2,
                        const float* __restrict__ Wout,
                        const float* __restrict__ bout,
                        float* __restrict__ out) {
    int gt   = blockIdx.x * blockDim.x + threadIdx.x;
    int g    = gt >> 5;
    int lane = gt & 31;
    if (g >= NGRAPH || lane >= NCLS) return;
    float cnt = g_cnt[g];
    float inv = cnt > 0.f ? 1.0f / cnt : 0.0f;
    float has = cnt > 0.f ? 1.0f : 0.0f;
    float acc = bout[lane];
    #pragma unroll
    for (int h = 0; h < HID; ++h) {
        float ph = g_pool[g * HID + h] * inv + has * b2[h];
        acc += ph * Wout[h * NCLS + lane];
    }
    out[g * NCLS + lane] = acc;
}

// ---------------------------------------------------------------------------
extern "C" void kernel_launch(void* const* d_in, const int* in_sizes, int n_in,
                              void* d_out, int out_size) {
    const float* x    = (const float*)d_in[0];
    const int*   ei   = (const int*)  d_in[1];   // int32 (JAX x64 disabled)
    const int*   bat  = (const int*)  d_in[2];
    const float* W1   = (const float*)d_in[3];
    const float* b1   = (const float*)d_in[4];
    const float* W2   = (const float*)d_in[5];
    const float* b2   = (const float*)d_in[6];
    const float* Wout = (const float*)d_in[7];
    const float* bout = (const float*)d_in[8];
    float* out = (float*)d_out;

    float* pa;  cudaGetSymbolAddress((void**)&pa, g_a);
    float* pb;  cudaGetSymbolAddress((void**)&pb, g_b);

    const int TB = 256;
    const int nblkN   = (N_NODES + TB - 1) / TB;
    const int nblkE   = (N_EDGES + TB - 1) / TB;
    const int nblkG   = (N_NODES + 63) / 64;
    const int nblkAgg = (N_EDGES * 32 + TB - 1) / TB;
    const int nblkPo  = (N_NODES * 32 + TB - 1) / TB;

    // degrees / norm
    k_deg_init <<<nblkN, TB>>>();
    k_deg_edges<<<nblkE, TB>>>(ei);
    k_dinv     <<<nblkN, TB>>>();

    // layer 1: gemm (+selfloop init fused), then edge aggregation
    k_gemm_fused<F_INDIM, false><<<nblkG, TB>>>(x, W1, nullptr, pa, pb);
    k_agg<<<nblkAgg, TB>>>(ei);

    // layer 2: gemm with fused relu(x+b1) input + selfloop init, then agg
    k_gemm_fused<HID, true><<<nblkG, TB>>>(pb, W2, b1, pa, pb);
    k_agg<<<nblkAgg, TB>>>(ei);

    // global mean pool + linear head (b2 folded in)
    k_pool_zero<<<(NGRAPH * HID + TB - 1) / TB, TB>>>();
    k_pool     <<<nblkPo, TB>>>(bat);
    k_final    <<<(NGRAPH * 32 + TB - 1) / TB, TB>>>(b2, Wout, bout, out);
}

// round 4
// speedup vs baseline: 1.6507x; 1.4438x over previous
#include <cuda_runtime.h>
#include <cstdint>

#define N_NODES 50000
#define N_EDGES 1600000
#define F_INDIM 128
#define HID     64
#define NCLS    19
#define NGRAPH  512

// ---- scratch (static device globals; no allocation) ----
__device__ float g_deg [N_NODES];
__device__ float g_dinv[N_NODES];
__device__ float g_a   [N_NODES * HID];   // gemm output / gather source
__device__ float g_b   [N_NODES * HID];   // aggregation target / activations
__device__ float g_pool[NGRAPH * HID];
__device__ float g_cnt [NGRAPH];

// Vectorized global reduction: one L2 atomic op per 16 bytes (sm_90+).
__device__ __forceinline__ void red_add_v4(float* addr, float4 v) {
    asm volatile("red.global.add.v4.f32 [%0], {%1, %2, %3, %4};"
                 :: "l"(addr), "f"(v.x), "f"(v.y), "f"(v.z), "f"(v.w)
                 : "memory");
}

// ---------------------------------------------------------------------------
__global__ void k_deg_init() {
    int i = blockIdx.x * blockDim.x + threadIdx.x;
    if (i < N_NODES) g_deg[i] = 1.0f;   // self-loop contributes 1
}

__global__ void k_deg_edges(const int* __restrict__ ei) {
    int e = blockIdx.x * blockDim.x + threadIdx.x;
    if (e < N_EDGES) atomicAdd(&g_deg[ei[N_EDGES + e]], 1.0f);
}

__global__ void k_dinv() {
    int i = blockIdx.x * blockDim.x + threadIdx.x;
    if (i < N_NODES) g_dinv[i] = rsqrtf(g_deg[i]);
}

// ---------------------------------------------------------------------------
// Register-tiled GEMM + fused epilogue.
//   out_a[n, 64] = act(X[n, K]) @ W[K, 64]
//   out_b[n, 64] = out_a[n, :] * dinv[n]^2          (self-loop init)
// act = relu(x + bias) when BIAS_RELU (layer 2 input), identity otherwise.
// Block = 256 threads = 64 nodes x 64 cols; thread tile = 4 nodes x 4 cols.
template <int K, bool BIAS_RELU>
__global__ void k_gemm_fused(const float* X, const float* __restrict__ W,
                             const float* __restrict__ bias,
                             float* out_a, float* out_b) {
    constexpr int XP = K + 4;             // padded pitch: spreads node rows over banks
    __shared__ float Xs[64 * XP];
    __shared__ float Ws[K * HID];
    const int tid = threadIdx.x;
    const int nb  = blockIdx.x * 64;

    for (int i = tid; i < K * HID; i += 256) Ws[i] = W[i];
    for (int i = tid; i < 64 * K; i += 256) {
        int nl = i / K, k = i % K;
        int node = nb + nl;
        float v = (node < N_NODES) ? X[node * K + k] : 0.0f;
        if (BIAS_RELU) { v += bias[k]; v = v > 0.f ? v : 0.f; }
        Xs[nl * XP + k] = v;
    }
    __syncthreads();

    const int ny0 = (tid / 16) * 4;       // 4 local nodes
    const int c0  = (tid & 15) * 4;       // 4 output cols

    float4 acc[4];
    #pragma unroll
    for (int i = 0; i < 4; ++i) acc[i] = make_float4(0.f, 0.f, 0.f, 0.f);

    #pragma unroll 4
    for (int k = 0; k < K; k += 4) {
        float4 xr[4], wr[4];
        #pragma unroll
        for (int i = 0; i < 4; ++i)
            xr[i] = *reinterpret_cast<const float4*>(&Xs[(ny0 + i) * XP + k]);
        #pragma unroll
        for (int j = 0; j < 4; ++j)
            wr[j] = *reinterpret_cast<const float4*>(&Ws[(k + j) * HID + c0]);
        #pragma unroll
        for (int i = 0; i < 4; ++i) {
            const float xk0 = xr[i].x, xk1 = xr[i].y, xk2 = xr[i].z, xk3 = xr[i].w;
            acc[i].x += xk0*wr[0].x + xk1*wr[1].x + xk2*wr[2].x + xk3*wr[3].x;
            acc[i].y += xk0*wr[0].y + xk1*wr[1].y + xk2*wr[2].y + xk3*wr[3].y;
            acc[i].z += xk0*wr[0].z + xk1*wr[1].z + xk2*wr[2].z + xk3*wr[3].z;
            acc[i].w += xk0*wr[0].w + xk1*wr[1].w + xk2*wr[2].w + xk3*wr[3].w;
        }
    }

    #pragma unroll
    for (int i = 0; i < 4; ++i) {
        int node = nb + ny0 + i;
        if (node >= N_NODES) break;
        *reinterpret_cast<float4*>(&out_a[node * HID + c0]) = acc[i];
        float di = g_dinv[node]; di *= di;
        float4 b = make_float4(acc[i].x*di, acc[i].y*di, acc[i].z*di, acc[i].w*di);
        *reinterpret_cast<float4*>(&out_b[node * HID + c0]) = b;
    }
}

// ---------------------------------------------------------------------------
// Half-warp per edge: 16 lanes gather one float4 each from g_a[src] (256 B
// coalesced), scale by norm, and red.v4 into g_b[dst]. 16 L2 atomic ops per
// edge-row instead of 64.
__global__ void k_agg(const int* __restrict__ ei) {
    int gt   = blockIdx.x * blockDim.x + threadIdx.x;
    int e    = gt >> 4;
    int lane = gt & 15;
    if (e >= N_EDGES) return;
    int s = ei[e];
    int d = ei[N_EDGES + e];
    float norm = g_dinv[s] * g_dinv[d];
    float4 v = *reinterpret_cast<const float4*>(&g_a[s * HID + lane * 4]);
    v.x *= norm; v.y *= norm; v.z *= norm; v.w *= norm;
    red_add_v4(&g_b[d * HID + lane * 4], v);
}

// ---------------------------------------------------------------------------
__global__ void k_pool_zero() {
    int i = blockIdx.x * blockDim.x + threadIdx.x;
    if (i < NGRAPH * HID) g_pool[i] = 0.f;
    if (i < NGRAPH)       g_cnt[i]  = 0.f;
}

// Half-warp per node: 16 float4 red ops into the graph's pool row.
__global__ void k_pool(const int* __restrict__ batch) {
    int gt   = blockIdx.x * blockDim.x + threadIdx.x;
    int n    = gt >> 4;
    int lane = gt & 15;
    if (n >= N_NODES) return;
    int g = batch[n];
    float4 v = *reinterpret_cast<const float4*>(&g_b[n * HID + lane * 4]);
    red_add_v4(&g_pool[g * HID + lane * 4], v);
    if (lane == 0) atomicAdd(&g_cnt[g], 1.0f);
}

// Warp per graph: out[g, c] = (mean(agg) + b2) @ W_out + b_out
__global__ void k_final(const float* __restrict__ b2,
                        const float* __restrict__ Wout,
                        const float* __restrict__ bout,
                        float* __restrict__ out) {
    int gt   = blockIdx.x * blockDim.x + threadIdx.x;
    int g    = gt >> 5;
    int lane = gt & 31;
    if (g >= NGRAPH || lane >= NCLS) return;
    float cnt = g_cnt[g];
    float inv = cnt > 0.f ? 1.0f / cnt : 0.0f;
    float has = cnt > 0.f ? 1.0f : 0.0f;
    float acc = bout[lane];
    #pragma unroll
    for (int h = 0; h < HID; ++h) {
        float ph = g_pool[g * HID + h] * inv + has * b2[h];
        acc += ph * Wout[h * NCLS + lane];
    }
    out[g * NCLS + lane] = acc;
}

// ---------------------------------------------------------------------------
extern "C" void kernel_launch(void* const* d_in, const int* in_sizes, int n_in,
                              void* d_out, int out_size) {
    const float* x    = (const float*)d_in[0];
    const int*   ei   = (const int*)  d_in[1];   // int32 (JAX x64 disabled)
    const int*   bat  = (const int*)  d_in[2];
    const float* W1   = (const float*)d_in[3];
    const float* b1   = (const float*)d_in[4];
    const float* W2   = (const float*)d_in[5];
    const float* b2   = (const float*)d_in[6];
    const float* Wout = (const float*)d_in[7];
    const float* bout = (const float*)d_in[8];
    float* out = (float*)d_out;

    float* pa;  cudaGetSymbolAddress((void**)&pa, g_a);
    float* pb;  cudaGetSymbolAddress((void**)&pb, g_b);

    const int TB = 256;
    const int nblkN   = (N_NODES + TB - 1) / TB;
    const int nblkE   = (N_EDGES + TB - 1) / TB;
    const int nblkG   = (N_NODES + 63) / 64;
    const long long aggT = (long long)N_EDGES * 16;
    const int nblkAgg = (int)((aggT + TB - 1) / TB);
    const int nblkPo  = (N_NODES * 16 + TB - 1) / TB;

    // degrees / norm
    k_deg_init <<<nblkN, TB>>>();
    k_deg_edges<<<nblkE, TB>>>(ei);
    k_dinv     <<<nblkN, TB>>>();

    // layer 1: gemm (+selfloop init fused), then edge aggregation
    k_gemm_fused<F_INDIM, false><<<nblkG, TB>>>(x, W1, nullptr, pa, pb);
    k_agg<<<nblkAgg, TB>>>(ei);

    // layer 2: gemm with fused relu(x+b1) input + selfloop init, then agg
    k_gemm_fused<HID, true><<<nblkG, TB>>>(pb, W2, b1, pa, pb);
    k_agg<<<nblkAgg, TB>>>(ei);

    // global mean pool + linear head (b2 folded in)
    k_pool_zero<<<(NGRAPH * HID + TB - 1) / TB, TB>>>();
    k_pool     <<<nblkPo, TB>>>(bat);
    k_final    <<<(NGRAPH * 32 + TB - 1) / TB, TB>>>(b2, Wout, bout, out);
}